// round 14
// baseline (speedup 1.0000x reference)
#include <cuda_runtime.h>
#include <cuda_fp16.h>
#include <math.h>
#include <stdint.h>

#define N_NODES 4681
#define BDIM    64
#define NS      16384
#define LEAF_START 585
#define N_PAR   585

typedef unsigned short u16;
typedef unsigned int   u32;
typedef unsigned long long u64;

// ---------------------------------------------------------------------------
// Static device scratch
// ---------------------------------------------------------------------------
__device__ __align__(256) float g_c  [(size_t)N_NODES*NS];
__device__ __align__(256) u16   g_hhi[(size_t)N_NODES*NS];
__device__ __align__(256) u16   g_xhi[(size_t)N_NODES*NS];
__device__ __align__(256) u16   g_hf [(size_t)4096*NS];
__device__ __align__(256) u16   g_fx [(size_t)N_PAR*NS];
__device__ __align__(256) u16   g_shi[(size_t)512*NS];
__device__ __align__(256) u16   g_iou[(size_t)512*BDIM*768];
__device__ __align__(256) u16 g_Wxh [768*256];
__device__ __align__(256) u16 g_Whh [768*256];
__device__ __align__(256) u16 g_Wfxh[256*256];
__device__ __align__(256) u16 g_Wfhh[256*256];

// ---------------------------------------------------------------------------
// Helpers
// ---------------------------------------------------------------------------
__device__ __forceinline__ float sig_fast(float x){ return 1.f/(1.f+__expf(-x)); }
__device__ __forceinline__ float tanh_fast(float x){ return 1.f - 2.f/(__expf(2.f*x)+1.f); }
__device__ __forceinline__ u16 f2h(float x){ __half h = __float2half_rn(x); return *(u16*)&h; }
__device__ __forceinline__ float h2f(u16 v){ __half h = *(__half*)&v; return __half2float(h); }

__device__ __forceinline__ u32 smem_u32(const void* p){
    u32 a; asm("{ .reg .u64 t; cvta.to.shared.u64 t, %1; cvt.u32.u64 %0, t; }" : "=r"(a) : "l"(p)); return a;
}
__device__ __forceinline__ void cp16(u32 d, const void* s){
    asm volatile("cp.async.cg.shared.global [%0], [%1], 16;" :: "r"(d), "l"(s));
}
__device__ __forceinline__ void cp_commit(){ asm volatile("cp.async.commit_group;" ::: "memory"); }
__device__ __forceinline__ void cp_wait0(){ asm volatile("cp.async.wait_group 0;" ::: "memory"); }
__device__ __forceinline__ void cp_wait1(){ asm volatile("cp.async.wait_group 1;" ::: "memory"); }

__device__ __forceinline__ void ldsm4(u32 &r0,u32 &r1,u32 &r2,u32 &r3, u32 addr){
    asm volatile("ldmatrix.sync.aligned.m8n8.x4.shared.b16 {%0,%1,%2,%3}, [%4];"
        : "=r"(r0),"=r"(r1),"=r"(r2),"=r"(r3) : "r"(addr));
}
__device__ __forceinline__ void mma16816(float* c, const u32* a, const u32* b){
    asm volatile("mma.sync.aligned.m16n8k16.row.col.f32.f16.f16.f32 "
        "{%0,%1,%2,%3}, {%4,%5,%6,%7}, {%8,%9}, {%0,%1,%2,%3};"
        : "+f"(c[0]),"+f"(c[1]),"+f"(c[2]),"+f"(c[3])
        : "r"(a[0]),"r"(a[1]),"r"(a[2]),"r"(a[3]), "r"(b[0]),"r"(b[1]));
}

#define SWZ(o) ((u32)(o) ^ (((u32)(o)>>3)&0x70u))

#define SMEM_PLAIN (65536 + 512)
#define SMEM_LEAF  (81920 + 768)

// ---------------------------------------------------------------------------
// Merged fp32 -> fp16 conversion
// ---------------------------------------------------------------------------
#define NX4  ((size_t)N_NODES*NS/4)
#define NW1  (768*256/4)
#define NW3  (256*256/4)
#define NSPLIT_TOT (NX4 + NW1*2 + NW3*2)

__global__ void split_all_kernel(
    const float* __restrict__ inputs,
    const float* __restrict__ Wioux, const float* __restrict__ Wiouh,
    const float* __restrict__ Wfx,   const float* __restrict__ Wfh,
    u16* __restrict__ xhi,
    u16* __restrict__ Wxh, u16* __restrict__ Whh,
    u16* __restrict__ Wfxh, u16* __restrict__ Wfhh)
{
    size_t i = (size_t)blockIdx.x*blockDim.x + threadIdx.x;
    if (i >= NSPLIT_TOT) return;
    const float* src; u16* dst; size_t k;
    if (i < NX4){ src=inputs; dst=xhi; k=i; }
    else {
        size_t r = i - NX4;
        if (r < NW1){ src=Wioux; dst=Wxh; k=r; }
        else if (r < 2*(size_t)NW1){ src=Wiouh; dst=Whh; k=r-NW1; }
        else if (r < 2*(size_t)NW1+NW3){ src=Wfx; dst=Wfxh; k=r-2*NW1; }
        else { src=Wfh; dst=Wfhh; k=r-2*NW1-NW3; }
    }
    float4 v = ((const float4*)src)[k];
    ((ushort4*)dst)[k] = make_ushort4(f2h(v.x), f2h(v.y), f2h(v.z), f2h(v.w));
}

// ---------------------------------------------------------------------------
// Chunk loaders (256 threads)
// ---------------------------------------------------------------------------
__device__ __forceinline__ void load_A_chunk(u32 aB, const u16* __restrict__ Ah,
    int rowBase, int kc, int M, int t)
{
#pragma unroll
    for (int i=0;i<4;i++){
        int e = t + i*256; int r = e>>3, s = e&7;
        int gr = rowBase + r; if (gr >= M) gr = M-1;
        cp16(aB + SWZ(r*128 + s*16), Ah + (size_t)gr*256 + kc + s*8);
    }
}
__device__ __forceinline__ void load_B_chunk128(u32 bB, const u16* __restrict__ Wh,
    int n0, int kc, int t)
{
#pragma unroll
    for (int i=0;i<4;i++){
        int e = t + i*256; int n = e>>3, s = e&7;
        cp16(bB + SWZ(n*128 + s*16), Wh + (size_t)(n0+n)*256 + kc + s*8);
    }
}

// ---------------------------------------------------------------------------
// Shared GEMM body: 256 threads, 8 warps (4m x 2n), warp tile 32x64.
// ---------------------------------------------------------------------------
__device__ __forceinline__ void gemm_body(
    char* smem,
    const u16* __restrict__ A1h, const u16* __restrict__ A2h,
    const u16* __restrict__ W1h, const u16* __restrict__ W2h,
    const float* __restrict__ b1, const float* __restrict__ b2,
    u16* __restrict__ Cout, int M, int ldc, int n0, int rowBase)
{
    const u32 sb = smem_u32(smem);
    const int t = threadIdx.x;
    float* biasS = (float*)(smem + 65536);

    for (int i=t;i<128;i+=256){
        float v = 0.f;
        if (b1) v += b1[n0+i];
        if (b2) v += b2[n0+i];
        biasS[i] = v;
    }

    float C[2][8][4];
#pragma unroll
    for (int a=0;a<2;a++)
#pragma unroll
    for (int b=0;b<8;b++)
#pragma unroll
    for (int cc=0;cc<4;cc++) C[a][b][cc]=0.f;

    const int nc = (A2h != nullptr) ? 8 : 4;

#define SEL_A(c) (((c)<4) ? A1h : A2h)
#define SEL_W(c) (((c)<4) ? W1h : W2h)
#define KC(c)    (((c)&3)*64)

    load_A_chunk(sb, SEL_A(0), rowBase, KC(0), M, t);
    load_B_chunk128(sb + 32768u, SEL_W(0), n0, KC(0), t);
    cp_commit();

    const int lane=t&31, wid=t>>5;
    const int wm=(wid&3)*32, wn=(wid>>2)*64;
    const u32 aRow  = (u32)(wm + (lane&15));
    const u32 aCol0 = (u32)((lane>>4)*16);
    const u32 bRow  = (u32)(wn + (lane&7) + ((lane>>4)&1)*8);
    const u32 bCol0 = (u32)(((lane>>3)&1)*16);

    for (int c=0;c<nc;c++){
        if (c+1<nc){
            int nb=(c+1)&1;
            load_A_chunk(sb + nb*16384u, SEL_A(c+1), rowBase, KC(c+1), M, t);
            load_B_chunk128(sb + 32768u + nb*16384u, SEL_W(c+1), n0, KC(c+1), t);
            cp_commit();
            cp_wait1();
        } else cp_wait0();
        __syncthreads();

        const u32 aB = sb + (u32)(c&1)*16384u;
        const u32 bB = sb + 32768u + (u32)(c&1)*16384u;
#pragma unroll
        for (int ks=0;ks<4;ks++){
            u32 a0[4], a1[4];
            ldsm4(a0[0],a0[1],a0[2],a0[3], aB + SWZ(aRow*128      + ks*32 + aCol0));
            ldsm4(a1[0],a1[1],a1[2],a1[3], aB + SWZ((aRow+16)*128 + ks*32 + aCol0));
#pragma unroll
            for (int nb=0;nb<4;nb++){
                u32 bf[4];
                ldsm4(bf[0],bf[1],bf[2],bf[3], bB + SWZ((bRow+nb*16)*128 + ks*32 + bCol0));
                mma16816(C[0][2*nb+0], a0, bf+0); mma16816(C[0][2*nb+1], a0, bf+2);
                mma16816(C[1][2*nb+0], a1, bf+0); mma16816(C[1][2*nb+1], a1, bf+2);
            }
        }
        if (c+1<nc) __syncthreads();
    }
#undef SEL_A
#undef SEL_W
#undef KC

#pragma unroll
    for (int mt=0;mt<2;mt++){
        int r0 = rowBase + wm + mt*16 + (lane>>2);
#pragma unroll
        for (int nt=0;nt<8;nt++){
            int cl = wn + nt*8 + (lane&3)*2;
            float bz0 = biasS[cl], bz1 = biasS[cl+1];
            if (r0 < M){
                u32 pk = (u32)f2h(C[mt][nt][0]+bz0) | ((u32)f2h(C[mt][nt][1]+bz1)<<16);
                *(u32*)(Cout + (size_t)r0*ldc + n0 + cl) = pk;
            }
            if (r0+8 < M){
                u32 pk = (u32)f2h(C[mt][nt][2]+bz0) | ((u32)f2h(C[mt][nt][3]+bz1)<<16);
                *(u32*)(Cout + (size_t)(r0+8)*ldc + n0 + cl) = pk;
            }
        }
    }
}

// ---------------------------------------------------------------------------
// gemm_pair: one launch = hf blocks + iou blocks + (fx blocks, d=3 only)
// ---------------------------------------------------------------------------
__global__ void __launch_bounds__(256,2) gemm_pair(
    int nHf, int nIou,
    const u16* __restrict__ hA, const u16* __restrict__ hW,
    u16* __restrict__ hC, int hM,
    const u16* __restrict__ iA1, const u16* __restrict__ iA2,
    const u16* __restrict__ iW1, const u16* __restrict__ iW2,
    const float* __restrict__ ib1, const float* __restrict__ ib2,
    u16* __restrict__ iC, int iM,
    const u16* __restrict__ fA, const u16* __restrict__ fW,
    const float* __restrict__ fB, u16* __restrict__ fC, int fM)
{
    extern __shared__ __align__(1024) char smem[];
    int bid = blockIdx.x;
    if (bid < nHf){
        gemm_body(smem, hA, nullptr, hW, nullptr, nullptr, nullptr,
                  hC, hM, 256, (bid&1)*128, (bid>>1)*128);
    } else if (bid < nHf + nIou){
        bid -= nHf;
        gemm_body(smem, iA1, iA2, iW1, iW2, ib1, ib2,
                  iC, iM, 768, (bid%6)*128, (bid/6)*128);
    } else {
        bid -= nHf + nIou;
        gemm_body(smem, fA, nullptr, fW, nullptr, fB, nullptr,
                  fC, fM, 256, (bid&1)*128, (bid>>1)*128);
    }
}

// ---------------------------------------------------------------------------
// gemm_leaf: fused iou GEMM + LSTM activation; h stored hi-only.
// ---------------------------------------------------------------------------
__global__ void __launch_bounds__(256,2) gemm_leaf(
    const u16* __restrict__ Ah_,
    const u16* __restrict__ Wh_,
    const float* __restrict__ bx, const float* __restrict__ bh,
    int M, int outRowBase)
{
    extern __shared__ __align__(1024) char smem[];
    const u32 sb = smem_u32(smem);
    const int t = threadIdx.x;
    const int m0 = blockIdx.x*64;
    const int rowBase = blockIdx.y*128;
    float* biasS = (float*)(smem + 81920);

    for (int i=t;i<192;i+=256){
        int g=i>>6, cc=i&63;
        biasS[i] = bx[g*256+m0+cc] + bh[g*256+m0+cc];
    }

    float Cg[3][2][4][4];
#pragma unroll
    for (int g=0;g<3;g++)
#pragma unroll
    for (int a=0;a<2;a++)
#pragma unroll
    for (int b=0;b<4;b++)
#pragma unroll
    for (int cc=0;cc<4;cc++) Cg[g][a][b][cc]=0.f;

#define LOAD_LEAF_B(bB, kc) \
    { _Pragma("unroll") \
      for (int i=0;i<6;i++){ \
        int e = t + i*256; int g = e>>9, f = e&511, n = f>>3, s = f&7; \
        cp16((bB) + (u32)g*8192u + SWZ(n*128 + s*16), \
             Wh_ + (size_t)(g*256 + m0 + n)*256 + (kc) + s*8); } }

    load_A_chunk(sb, Ah_, rowBase, 0, M, t);
    LOAD_LEAF_B(sb + 32768u, 0);
    cp_commit();

    const int lane=t&31, wid=t>>5;
    const int wm=(wid&3)*32, wn=(wid>>2)*32;
    const u32 aRow  = (u32)(wm + (lane&15));
    const u32 aCol0 = (u32)((lane>>4)*16);
    const u32 bRow  = (u32)(wn + (lane&7) + ((lane>>4)&1)*8);
    const u32 bCol0 = (u32)(((lane>>3)&1)*16);

    for (int c=0;c<4;c++){
        cp_wait0();
        __syncthreads();
        if (c+1<4){
            int nb=(c+1)&1;
            load_A_chunk(sb + nb*16384u, Ah_, rowBase, (c+1)*64, M, t);
            LOAD_LEAF_B(sb + 32768u + (u32)nb*24576u, (c+1)*64);
            cp_commit();
        }
        const u32 aB = sb + (u32)(c&1)*16384u;
        const u32 bB = sb + 32768u + (u32)(c&1)*24576u;
#pragma unroll
        for (int ks=0;ks<4;ks++){
            u32 a0[4], a1[4];
            ldsm4(a0[0],a0[1],a0[2],a0[3], aB + SWZ(aRow*128      + ks*32 + aCol0));
            ldsm4(a1[0],a1[1],a1[2],a1[3], aB + SWZ((aRow+16)*128 + ks*32 + aCol0));
#pragma unroll
            for (int g=0;g<3;g++){
                u32 b0[4], b1f[4];
                u32 gB = bB + (u32)g*8192u;
                ldsm4(b0[0],b0[1],b0[2],b0[3],   gB + SWZ(bRow*128      + ks*32 + bCol0));
                ldsm4(b1f[0],b1f[1],b1f[2],b1f[3], gB + SWZ((bRow+16)*128 + ks*32 + bCol0));
                mma16816(Cg[g][0][0], a0, b0+0); mma16816(Cg[g][0][1], a0, b0+2);
                mma16816(Cg[g][0][2], a0, b1f+0); mma16816(Cg[g][0][3], a0, b1f+2);
                mma16816(Cg[g][1][0], a1, b0+0); mma16816(Cg[g][1][1], a1, b0+2);
                mma16816(Cg[g][1][2], a1, b1f+0); mma16816(Cg[g][1][3], a1, b1f+2);
            }
        }
    }
#undef LOAD_LEAF_B

#pragma unroll
    for (int mt=0;mt<2;mt++){
        int rb = wm + mt*16 + (lane>>2);
#pragma unroll
        for (int h2=0;h2<2;h2++){
            int row = rowBase + rb + h2*8;
#pragma unroll
            for (int nt=0;nt<4;nt++){
                int cl = wn + nt*8 + (lane&3)*2;
                float cs2[2]; u16 hh2[2];
#pragma unroll
                for (int e=0;e<2;e++){
                    float iv = Cg[0][mt][nt][h2*2+e] + biasS[cl+e];
                    float ov = Cg[1][mt][nt][h2*2+e] + biasS[64+cl+e];
                    float uv = Cg[2][mt][nt][h2*2+e] + biasS[128+cl+e];
                    float c_ = sig_fast(iv)*tanh_fast(uv);
                    float h_ = sig_fast(ov)*tanh_fast(c_);
                    cs2[e]=c_;
                    hh2[e]=f2h(h_);
                }
                size_t idx = ((size_t)(outRowBase+row))*256 + m0 + cl;
                *(float2*)(g_c+idx) = make_float2(cs2[0],cs2[1]);
                *(u32*)(g_hhi+idx)  = (u32)hh2[0] | ((u32)hh2[1]<<16);
            }
        }
    }
}

// ---------------------------------------------------------------------------
// hsum (d=3 only: children are leaves): reads h-hi; fp16 output
// ---------------------------------------------------------------------------
__global__ void hsum_kernel(const float* __restrict__ prob, int s, int cnt)
{
    int idx = blockIdx.x*blockDim.x + threadIdx.x;
    if (idx >= cnt*NS) return;
    int p = idx >> 14, r = idx & (NS-1);
    int pg = s + p, cg = 8*pg + 1;
    const float* pr = prob + (size_t)pg*N_NODES + cg;
    float acc = 0.f;
#pragma unroll
    for (int j=0;j<8;j++)
        acc += pr[j] * h2f(g_hhi[(size_t)(cg+j)*NS + r]);
    g_shi[idx] = f2h(acc);
}

// ---------------------------------------------------------------------------
// final_hsum: finalize level-d nodes (8 siblings per parent) AND produce the
//   parent's hsum (level d-1) in the same kernel.
//   Block = (parent bp, r-chunk rc); thread t -> r = rc*256+t.
//   s = level-d start; sloc(sibling j local) = 8*bp + j; global = s + sloc.
//   writeOut != 0: d==0 path handled by final_root instead.
// ---------------------------------------------------------------------------
__global__ void final_hsum_kernel(const float* __restrict__ prob,
                                  const float* __restrict__ bfh,
                                  int s, int sp)   // level-d start, parent level start
{
    int bp = blockIdx.x;             // parent local index (level d-1)
    int rc = blockIdx.y;             // r-chunk
    int t  = threadIdx.x;
    int r  = rc*256 + t;
    int m  = r & 255;
    float bf = bfh[m];

    int pg_par = sp + bp;                       // global parent node
    const float* pw_par = prob + (size_t)pg_par*N_NODES + (8*pg_par+1);

    float hsum_acc = 0.f;
#pragma unroll
    for (int j=0;j<8;j++){
        int sloc = 8*bp + j;                    // level-d local node
        int pg   = s + sloc;                    // global node
        int cg   = 8*pg + 1;                    // its children (level d+1)
        int row  = sloc*64 + (r>>8);            // iou row

        const u16* iou = g_iou + (size_t)row*768 + m;
        float iv = h2f(iou[0]), ov = h2f(iou[256]), uv = h2f(iou[512]);
        float fxv = h2f(g_fx[(size_t)pg*NS + r]);

        const float* pr = prob + (size_t)pg*N_NODES + cg;
        float acc = 0.f;
#pragma unroll
        for (int k=0;k<8;k++){
            float pw  = pr[k];
            float hf  = h2f(g_hf[(size_t)(8*sloc+k)*NS + r]);
            float cch = g_c[(size_t)(cg+k)*NS + r];
            float f = sig_fast(pw*hf + bf + fxv);
            acc += f * pw * cch;
        }
        float cc = sig_fast(iv)*tanh_fast(uv) + acc;
        float hh = sig_fast(ov)*tanh_fast(cc);
        g_c[(size_t)pg*NS + r]   = cc;
        g_hhi[(size_t)pg*NS + r] = f2h(hh);
        hsum_acc += pw_par[j] * hh;
    }
    g_shi[(size_t)bp*NS + r] = f2h(hsum_acc);
}

// ---------------------------------------------------------------------------
// final_root: finalize node 0 and write out directly.
// ---------------------------------------------------------------------------
__global__ void final_root_kernel(const float* __restrict__ prob,
                                  const float* __restrict__ bfh,
                                  float* __restrict__ out)
{
    int r = blockIdx.x*blockDim.x + threadIdx.x;
    if (r >= NS) return;
    int m = r & 255;

    const u16* iou = g_iou + (size_t)(r>>8)*768 + m;
    float iv = h2f(iou[0]), ov = h2f(iou[256]), uv = h2f(iou[512]);
    float fxv = h2f(g_fx[r]);
    float bf = bfh[m];

    const float* pr = prob + 1;   // prob[0, 1..8]
    float acc = 0.f;
#pragma unroll
    for (int j=0;j<8;j++){
        float pw  = pr[j];
        float hf  = h2f(g_hf[(size_t)j*NS + r]);
        float cch = g_c[(size_t)(1+j)*NS + r];
        float f = sig_fast(pw*hf + bf + fxv);
        acc += f * pw * cch;
    }
    float cc = sig_fast(iv)*tanh_fast(uv) + acc;
    float hh = sig_fast(ov)*tanh_fast(cc);
    out[r]      = cc;
    out[NS + r] = hh;
}

// ---------------------------------------------------------------------------
// kernel_launch
// ---------------------------------------------------------------------------
extern "C" void kernel_launch(void* const* d_in, const int* in_sizes, int n_in,
                              void* d_out, int out_size)
{
    const float* inputs = (const float*)d_in[0];
    const float* prob   = (const float*)d_in[1];
    const float* Wioux  = (const float*)d_in[2];
    const float* bioux  = (const float*)d_in[3];
    const float* Wiouh  = (const float*)d_in[4];
    const float* biouh  = (const float*)d_in[5];
    const float* Wfx    = (const float*)d_in[6];
    const float* bfx    = (const float*)d_in[7];
    const float* Wfh    = (const float*)d_in[8];
    const float* bfh    = (const float*)d_in[9];
    float* out = (float*)d_out;

    u16 *pxhi,*phhi,*pshi,*phf,*pfx,*piou;
    u16 *pWxh,*pWhh,*pWfxh,*pWfhh;
    cudaGetSymbolAddress((void**)&pxhi,  g_xhi);
    cudaGetSymbolAddress((void**)&phhi,  g_hhi);
    cudaGetSymbolAddress((void**)&pshi,  g_shi);
    cudaGetSymbolAddress((void**)&pWxh,  g_Wxh);
    cudaGetSymbolAddress((void**)&pWhh,  g_Whh);
    cudaGetSymbolAddress((void**)&pWfxh, g_Wfxh);
    cudaGetSymbolAddress((void**)&pWfhh, g_Wfhh);
    cudaGetSymbolAddress((void**)&phf,   g_hf);
    cudaGetSymbolAddress((void**)&pfx,   g_fx);
    cudaGetSymbolAddress((void**)&piou,  g_iou);

    cudaFuncSetAttribute(gemm_pair, cudaFuncAttributeMaxDynamicSharedMemorySize, SMEM_PLAIN);
    cudaFuncSetAttribute(gemm_leaf, cudaFuncAttributeMaxDynamicSharedMemorySize, SMEM_LEAF);

    const int MPAR = N_PAR*BDIM;   // 37440

    // 0: merged fp16 conversion
    split_all_kernel<<<(unsigned)((NSPLIT_TOT+255)/256),256>>>(
        inputs, Wioux, Wiouh, Wfx, Wfh,
        pxhi, pWxh, pWhh, pWfxh, pWfhh);

    // 1: leaf level fused GEMM + activation
    gemm_leaf<<<dim3(4,2048),256,SMEM_LEAF>>>(
        pxhi + (size_t)LEAF_START*NS,
        pWxh, bioux, biouh, 4096*BDIM, LEAF_START*BDIM);

    const int starts[5] = {0, 1, 9, 73, 585};
    const int counts[5] = {1, 8, 64, 512, 4096};

    for (int d=3; d>=0; d--){
        int s = starts[d], cnt = counts[d], cs = starts[d+1];
        int Mh = cnt*8*BDIM, Mp = cnt*BDIM;

        if (d == 3){
            // hsum over leaf h  (launch #2)
            hsum_kernel<<<(cnt*NS+255)/256,256>>>(prob, s, cnt);
        }
        // else: g_shi already produced by previous final_hsum

        // merged GEMMs: hf + iou (+ fx on d=3)  (launch #3 on d=3)
        int nHf  = 2*((Mh+127)/128);
        int nIou = 6*((Mp+127)/128);
        int nFx  = (d==3) ? 2*((MPAR+127)/128) : 0;
        gemm_pair<<<nHf+nIou+nFx,256,SMEM_PLAIN>>>(
            nHf, nIou,
            phhi + (size_t)cs*NS, pWfhh, phf, Mh,
            pxhi + (size_t)s*NS, pshi, pWxh, pWhh,
            bioux, biouh, piou, Mp,
            pxhi, pWfxh, bfx, pfx, MPAR);

        if (d > 0){
            // finalize level d + produce hsum for level d-1
            int pcnt = cnt/8;
            final_hsum_kernel<<<dim3(pcnt,64),256>>>(prob, bfh, s, starts[d-1]);
        } else {
            final_root_kernel<<<(NS+255)/256,256>>>(prob, bfh, out);
        }
    }
}

// round 15
// speedup vs baseline: 1.0245x; 1.0245x over previous
#include <cuda_runtime.h>
#include <cuda_fp16.h>
#include <math.h>
#include <stdint.h>

#define N_NODES 4681
#define BDIM    64
#define NS      16384
#define LEAF_START 585
#define N_PAR   585

typedef unsigned short u16;
typedef unsigned int   u32;
typedef unsigned long long u64;

// ---------------------------------------------------------------------------
// Static device scratch
// ---------------------------------------------------------------------------
__device__ __align__(256) float g_c  [(size_t)N_NODES*NS];
__device__ __align__(256) u16   g_hhi[(size_t)N_NODES*NS];
__device__ __align__(256) u16   g_xhi[(size_t)N_NODES*NS];
__device__ __align__(256) u16   g_hf [(size_t)4096*NS];
__device__ __align__(256) u16   g_fx [(size_t)N_PAR*NS];
__device__ __align__(256) u16   g_shi[(size_t)512*NS];
__device__ __align__(256) u16   g_iou[(size_t)512*BDIM*768];
__device__ __align__(256) u16 g_Wxh [768*256];
__device__ __align__(256) u16 g_Whh [768*256];
__device__ __align__(256) u16 g_Wfxh[256*256];
__device__ __align__(256) u16 g_Wfhh[256*256];

// ---------------------------------------------------------------------------
// Helpers
// ---------------------------------------------------------------------------
__device__ __forceinline__ float sig_fast(float x){ return 1.f/(1.f+__expf(-x)); }
__device__ __forceinline__ float tanh_fast(float x){ return 1.f - 2.f/(__expf(2.f*x)+1.f); }
__device__ __forceinline__ u16 f2h(float x){ __half h = __float2half_rn(x); return *(u16*)&h; }
__device__ __forceinline__ float h2f(u16 v){ __half h = *(__half*)&v; return __half2float(h); }

__device__ __forceinline__ u32 smem_u32(const void* p){
    u32 a; asm("{ .reg .u64 t; cvta.to.shared.u64 t, %1; cvt.u32.u64 %0, t; }" : "=r"(a) : "l"(p)); return a;
}
__device__ __forceinline__ void cp16(u32 d, const void* s){
    asm volatile("cp.async.cg.shared.global [%0], [%1], 16;" :: "r"(d), "l"(s));
}
__device__ __forceinline__ void cp_commit(){ asm volatile("cp.async.commit_group;" ::: "memory"); }
__device__ __forceinline__ void cp_wait0(){ asm volatile("cp.async.wait_group 0;" ::: "memory"); }
__device__ __forceinline__ void cp_wait1(){ asm volatile("cp.async.wait_group 1;" ::: "memory"); }

__device__ __forceinline__ void ldsm4(u32 &r0,u32 &r1,u32 &r2,u32 &r3, u32 addr){
    asm volatile("ldmatrix.sync.aligned.m8n8.x4.shared.b16 {%0,%1,%2,%3}, [%4];"
        : "=r"(r0),"=r"(r1),"=r"(r2),"=r"(r3) : "r"(addr));
}
__device__ __forceinline__ void mma16816(float* c, const u32* a, const u32* b){
    asm volatile("mma.sync.aligned.m16n8k16.row.col.f32.f16.f16.f32 "
        "{%0,%1,%2,%3}, {%4,%5,%6,%7}, {%8,%9}, {%0,%1,%2,%3};"
        : "+f"(c[0]),"+f"(c[1]),"+f"(c[2]),"+f"(c[3])
        : "r"(a[0]),"r"(a[1]),"r"(a[2]),"r"(a[3]), "r"(b[0]),"r"(b[1]));
}

#define SWZ(o) ((u32)(o) ^ (((u32)(o)>>3)&0x70u))

#define SMEM_PLAIN (65536 + 512)
#define SMEM_LEAF  (81920 + 768)

// ---------------------------------------------------------------------------
// Merged fp32 -> fp16 conversion
// ---------------------------------------------------------------------------
#define NX4  ((size_t)N_NODES*NS/4)
#define NW1  (768*256/4)
#define NW3  (256*256/4)
#define NSPLIT_TOT (NX4 + NW1*2 + NW3*2)

__global__ void split_all_kernel(
    const float* __restrict__ inputs,
    const float* __restrict__ Wioux, const float* __restrict__ Wiouh,
    const float* __restrict__ Wfx,   const float* __restrict__ Wfh,
    u16* __restrict__ xhi,
    u16* __restrict__ Wxh, u16* __restrict__ Whh,
    u16* __restrict__ Wfxh, u16* __restrict__ Wfhh)
{
    size_t i = (size_t)blockIdx.x*blockDim.x + threadIdx.x;
    if (i >= NSPLIT_TOT) return;
    const float* src; u16* dst; size_t k;
    if (i < NX4){ src=inputs; dst=xhi; k=i; }
    else {
        size_t r = i - NX4;
        if (r < NW1){ src=Wioux; dst=Wxh; k=r; }
        else if (r < 2*(size_t)NW1){ src=Wiouh; dst=Whh; k=r-NW1; }
        else if (r < 2*(size_t)NW1+NW3){ src=Wfx; dst=Wfxh; k=r-2*NW1; }
        else { src=Wfh; dst=Wfhh; k=r-2*NW1-NW3; }
    }
    float4 v = ((const float4*)src)[k];
    ((ushort4*)dst)[k] = make_ushort4(f2h(v.x), f2h(v.y), f2h(v.z), f2h(v.w));
}

// ---------------------------------------------------------------------------
// Chunk loaders (256 threads)
// ---------------------------------------------------------------------------
__device__ __forceinline__ void load_A_chunk(u32 aB, const u16* __restrict__ Ah,
    int rowBase, int kc, int M, int t)
{
#pragma unroll
    for (int i=0;i<4;i++){
        int e = t + i*256; int r = e>>3, s = e&7;
        int gr = rowBase + r; if (gr >= M) gr = M-1;
        cp16(aB + SWZ(r*128 + s*16), Ah + (size_t)gr*256 + kc + s*8);
    }
}
__device__ __forceinline__ void load_B_chunk128(u32 bB, const u16* __restrict__ Wh,
    int n0, int kc, int t)
{
#pragma unroll
    for (int i=0;i<4;i++){
        int e = t + i*256; int n = e>>3, s = e&7;
        cp16(bB + SWZ(n*128 + s*16), Wh + (size_t)(n0+n)*256 + kc + s*8);
    }
}

// ---------------------------------------------------------------------------
// Shared GEMM body: 256 threads, 8 warps (4m x 2n), warp tile 32x64.
// ---------------------------------------------------------------------------
__device__ __forceinline__ void gemm_body(
    char* smem,
    const u16* __restrict__ A1h, const u16* __restrict__ A2h,
    const u16* __restrict__ W1h, const u16* __restrict__ W2h,
    const float* __restrict__ b1, const float* __restrict__ b2,
    u16* __restrict__ Cout, int M, int ldc, int n0, int rowBase)
{
    const u32 sb = smem_u32(smem);
    const int t = threadIdx.x;
    float* biasS = (float*)(smem + 65536);

    for (int i=t;i<128;i+=256){
        float v = 0.f;
        if (b1) v += b1[n0+i];
        if (b2) v += b2[n0+i];
        biasS[i] = v;
    }

    float C[2][8][4];
#pragma unroll
    for (int a=0;a<2;a++)
#pragma unroll
    for (int b=0;b<8;b++)
#pragma unroll
    for (int cc=0;cc<4;cc++) C[a][b][cc]=0.f;

    const int nc = (A2h != nullptr) ? 8 : 4;

#define SEL_A(c) (((c)<4) ? A1h : A2h)
#define SEL_W(c) (((c)<4) ? W1h : W2h)
#define KC(c)    (((c)&3)*64)

    load_A_chunk(sb, SEL_A(0), rowBase, KC(0), M, t);
    load_B_chunk128(sb + 32768u, SEL_W(0), n0, KC(0), t);
    cp_commit();

    const int lane=t&31, wid=t>>5;
    const int wm=(wid&3)*32, wn=(wid>>2)*64;
    const u32 aRow  = (u32)(wm + (lane&15));
    const u32 aCol0 = (u32)((lane>>4)*16);
    const u32 bRow  = (u32)(wn + (lane&7) + ((lane>>4)&1)*8);
    const u32 bCol0 = (u32)(((lane>>3)&1)*16);

    for (int c=0;c<nc;c++){
        if (c+1<nc){
            int nb=(c+1)&1;
            load_A_chunk(sb + nb*16384u, SEL_A(c+1), rowBase, KC(c+1), M, t);
            load_B_chunk128(sb + 32768u + nb*16384u, SEL_W(c+1), n0, KC(c+1), t);
            cp_commit();
            cp_wait1();
        } else cp_wait0();
        __syncthreads();

        const u32 aB = sb + (u32)(c&1)*16384u;
        const u32 bB = sb + 32768u + (u32)(c&1)*16384u;
#pragma unroll
        for (int ks=0;ks<4;ks++){
            u32 a0[4], a1[4];
            ldsm4(a0[0],a0[1],a0[2],a0[3], aB + SWZ(aRow*128      + ks*32 + aCol0));
            ldsm4(a1[0],a1[1],a1[2],a1[3], aB + SWZ((aRow+16)*128 + ks*32 + aCol0));
#pragma unroll
            for (int nb=0;nb<4;nb++){
                u32 bf[4];
                ldsm4(bf[0],bf[1],bf[2],bf[3], bB + SWZ((bRow+nb*16)*128 + ks*32 + bCol0));
                mma16816(C[0][2*nb+0], a0, bf+0); mma16816(C[0][2*nb+1], a0, bf+2);
                mma16816(C[1][2*nb+0], a1, bf+0); mma16816(C[1][2*nb+1], a1, bf+2);
            }
        }
        if (c+1<nc) __syncthreads();
    }
#undef SEL_A
#undef SEL_W
#undef KC

#pragma unroll
    for (int mt=0;mt<2;mt++){
        int r0 = rowBase + wm + mt*16 + (lane>>2);
#pragma unroll
        for (int nt=0;nt<8;nt++){
            int cl = wn + nt*8 + (lane&3)*2;
            float bz0 = biasS[cl], bz1 = biasS[cl+1];
            if (r0 < M){
                u32 pk = (u32)f2h(C[mt][nt][0]+bz0) | ((u32)f2h(C[mt][nt][1]+bz1)<<16);
                *(u32*)(Cout + (size_t)r0*ldc + n0 + cl) = pk;
            }
            if (r0+8 < M){
                u32 pk = (u32)f2h(C[mt][nt][2]+bz0) | ((u32)f2h(C[mt][nt][3]+bz1)<<16);
                *(u32*)(Cout + (size_t)(r0+8)*ldc + n0 + cl) = pk;
            }
        }
    }
}

// ---------------------------------------------------------------------------
// gemm_pair: one launch = hf blocks + iou blocks + (fx blocks, d=3 only)
// ---------------------------------------------------------------------------
__global__ void __launch_bounds__(256,2) gemm_pair(
    int nHf, int nIou,
    const u16* __restrict__ hA, const u16* __restrict__ hW,
    u16* __restrict__ hC, int hM,
    const u16* __restrict__ iA1, const u16* __restrict__ iA2,
    const u16* __restrict__ iW1, const u16* __restrict__ iW2,
    const float* __restrict__ ib1, const float* __restrict__ ib2,
    u16* __restrict__ iC, int iM,
    const u16* __restrict__ fA, const u16* __restrict__ fW,
    const float* __restrict__ fB, u16* __restrict__ fC, int fM)
{
    extern __shared__ __align__(1024) char smem[];
    int bid = blockIdx.x;
    if (bid < nHf){
        gemm_body(smem, hA, nullptr, hW, nullptr, nullptr, nullptr,
                  hC, hM, 256, (bid&1)*128, (bid>>1)*128);
    } else if (bid < nHf + nIou){
        bid -= nHf;
        gemm_body(smem, iA1, iA2, iW1, iW2, ib1, ib2,
                  iC, iM, 768, (bid%6)*128, (bid/6)*128);
    } else {
        bid -= nHf + nIou;
        gemm_body(smem, fA, nullptr, fW, nullptr, fB, nullptr,
                  fC, fM, 256, (bid&1)*128, (bid>>1)*128);
    }
}

// ---------------------------------------------------------------------------
// gemm_leaf: fused iou GEMM + LSTM activation; h stored hi-only.
// ---------------------------------------------------------------------------
__global__ void __launch_bounds__(256,2) gemm_leaf(
    const u16* __restrict__ Ah_,
    const u16* __restrict__ Wh_,
    const float* __restrict__ bx, const float* __restrict__ bh,
    int M, int outRowBase)
{
    extern __shared__ __align__(1024) char smem[];
    const u32 sb = smem_u32(smem);
    const int t = threadIdx.x;
    const int m0 = blockIdx.x*64;
    const int rowBase = blockIdx.y*128;
    float* biasS = (float*)(smem + 81920);

    for (int i=t;i<192;i+=256){
        int g=i>>6, cc=i&63;
        biasS[i] = bx[g*256+m0+cc] + bh[g*256+m0+cc];
    }

    float Cg[3][2][4][4];
#pragma unroll
    for (int g=0;g<3;g++)
#pragma unroll
    for (int a=0;a<2;a++)
#pragma unroll
    for (int b=0;b<4;b++)
#pragma unroll
    for (int cc=0;cc<4;cc++) Cg[g][a][b][cc]=0.f;

#define LOAD_LEAF_B(bB, kc) \
    { _Pragma("unroll") \
      for (int i=0;i<6;i++){ \
        int e = t + i*256; int g = e>>9, f = e&511, n = f>>3, s = f&7; \
        cp16((bB) + (u32)g*8192u + SWZ(n*128 + s*16), \
             Wh_ + (size_t)(g*256 + m0 + n)*256 + (kc) + s*8); } }

    load_A_chunk(sb, Ah_, rowBase, 0, M, t);
    LOAD_LEAF_B(sb + 32768u, 0);
    cp_commit();

    const int lane=t&31, wid=t>>5;
    const int wm=(wid&3)*32, wn=(wid>>2)*32;
    const u32 aRow  = (u32)(wm + (lane&15));
    const u32 aCol0 = (u32)((lane>>4)*16);
    const u32 bRow  = (u32)(wn + (lane&7) + ((lane>>4)&1)*8);
    const u32 bCol0 = (u32)(((lane>>3)&1)*16);

    for (int c=0;c<4;c++){
        cp_wait0();
        __syncthreads();
        if (c+1<4){
            int nb=(c+1)&1;
            load_A_chunk(sb + nb*16384u, Ah_, rowBase, (c+1)*64, M, t);
            LOAD_LEAF_B(sb + 32768u + (u32)nb*24576u, (c+1)*64);
            cp_commit();
        }
        const u32 aB = sb + (u32)(c&1)*16384u;
        const u32 bB = sb + 32768u + (u32)(c&1)*24576u;
#pragma unroll
        for (int ks=0;ks<4;ks++){
            u32 a0[4], a1[4];
            ldsm4(a0[0],a0[1],a0[2],a0[3], aB + SWZ(aRow*128      + ks*32 + aCol0));
            ldsm4(a1[0],a1[1],a1[2],a1[3], aB + SWZ((aRow+16)*128 + ks*32 + aCol0));
#pragma unroll
            for (int g=0;g<3;g++){
                u32 b0[4], b1f[4];
                u32 gB = bB + (u32)g*8192u;
                ldsm4(b0[0],b0[1],b0[2],b0[3],   gB + SWZ(bRow*128      + ks*32 + bCol0));
                ldsm4(b1f[0],b1f[1],b1f[2],b1f[3], gB + SWZ((bRow+16)*128 + ks*32 + bCol0));
                mma16816(Cg[g][0][0], a0, b0+0); mma16816(Cg[g][0][1], a0, b0+2);
                mma16816(Cg[g][0][2], a0, b1f+0); mma16816(Cg[g][0][3], a0, b1f+2);
                mma16816(Cg[g][1][0], a1, b0+0); mma16816(Cg[g][1][1], a1, b0+2);
                mma16816(Cg[g][1][2], a1, b1f+0); mma16816(Cg[g][1][3], a1, b1f+2);
            }
        }
    }
#undef LOAD_LEAF_B

#pragma unroll
    for (int mt=0;mt<2;mt++){
        int rb = wm + mt*16 + (lane>>2);
#pragma unroll
        for (int h2=0;h2<2;h2++){
            int row = rowBase + rb + h2*8;
#pragma unroll
            for (int nt=0;nt<4;nt++){
                int cl = wn + nt*8 + (lane&3)*2;
                float cs2[2]; u16 hh2[2];
#pragma unroll
                for (int e=0;e<2;e++){
                    float iv = Cg[0][mt][nt][h2*2+e] + biasS[cl+e];
                    float ov = Cg[1][mt][nt][h2*2+e] + biasS[64+cl+e];
                    float uv = Cg[2][mt][nt][h2*2+e] + biasS[128+cl+e];
                    float c_ = sig_fast(iv)*tanh_fast(uv);
                    float h_ = sig_fast(ov)*tanh_fast(c_);
                    cs2[e]=c_;
                    hh2[e]=f2h(h_);
                }
                size_t idx = ((size_t)(outRowBase+row))*256 + m0 + cl;
                *(float2*)(g_c+idx) = make_float2(cs2[0],cs2[1]);
                *(u32*)(g_hhi+idx)  = (u32)hh2[0] | ((u32)hh2[1]<<16);
            }
        }
    }
}

// ---------------------------------------------------------------------------
// hsum: reads h-hi; fp16 output
// ---------------------------------------------------------------------------
__global__ void hsum_kernel(const float* __restrict__ prob, int s, int cnt)
{
    int idx = blockIdx.x*blockDim.x + threadIdx.x;
    if (idx >= cnt*NS) return;
    int p = idx >> 14, r = idx & (NS-1);
    int pg = s + p, cg = 8*pg + 1;
    const float* pr = prob + (size_t)pg*N_NODES + cg;
    float acc = 0.f;
#pragma unroll
    for (int j=0;j<8;j++)
        acc += pr[j] * h2f(g_hhi[(size_t)(cg+j)*NS + r]);
    g_shi[idx] = f2h(acc);
}

// ---------------------------------------------------------------------------
// final: forget gates + cell/hidden activation (levels d=3..1)
// ---------------------------------------------------------------------------
__global__ void final_kernel(const float* __restrict__ prob,
                             const float* __restrict__ bfh, int s, int cnt)
{
    int idx = blockIdx.x*blockDim.x + threadIdx.x;
    if (idx >= cnt*NS) return;
    int p = idx >> 14, r = idx & (NS-1);
    int m = idx & 255;
    int row = idx >> 8;
    int pg = s + p, cg = 8*pg + 1;

    const u16* iou = g_iou + (size_t)row*768 + m;
    float iv = h2f(iou[0]), ov = h2f(iou[256]), uv = h2f(iou[512]);
    float fxv = h2f(g_fx[(size_t)pg*NS + r]);
    float bf = bfh[m];

    const float* pr = prob + (size_t)pg*N_NODES + cg;
    float acc = 0.f;
#pragma unroll
    for (int j=0;j<8;j++){
        float pw  = pr[j];
        float hf  = h2f(g_hf[(size_t)(8*p+j)*NS + r]);
        float cch = g_c[(size_t)(cg+j)*NS + r];
        float f = sig_fast(pw*hf + bf + fxv);
        acc += f * pw * cch;
    }
    float cc = sig_fast(iv)*tanh_fast(uv) + acc;
    float hh = sig_fast(ov)*tanh_fast(cc);
    g_c[(size_t)pg*NS + r] = cc;
    g_hhi[(size_t)pg*NS + r] = f2h(hh);
}

// ---------------------------------------------------------------------------
// final_root: finalize node 0 and write out directly.
// ---------------------------------------------------------------------------
__global__ void final_root_kernel(const float* __restrict__ prob,
                                  const float* __restrict__ bfh,
                                  float* __restrict__ out)
{
    int r = blockIdx.x*blockDim.x + threadIdx.x;
    if (r >= NS) return;
    int m = r & 255;

    const u16* iou = g_iou + (size_t)(r>>8)*768 + m;
    float iv = h2f(iou[0]), ov = h2f(iou[256]), uv = h2f(iou[512]);
    float fxv = h2f(g_fx[r]);
    float bf = bfh[m];

    const float* pr = prob + 1;   // prob[0, 1..8]
    float acc = 0.f;
#pragma unroll
    for (int j=0;j<8;j++){
        float pw  = pr[j];
        float hf  = h2f(g_hf[(size_t)j*NS + r]);
        float cch = g_c[(size_t)(1+j)*NS + r];
        float f = sig_fast(pw*hf + bf + fxv);
        acc += f * pw * cch;
    }
    float cc = sig_fast(iv)*tanh_fast(uv) + acc;
    float hh = sig_fast(ov)*tanh_fast(cc);
    out[r]      = cc;
    out[NS + r] = hh;
}

// ---------------------------------------------------------------------------
// kernel_launch
// ---------------------------------------------------------------------------
extern "C" void kernel_launch(void* const* d_in, const int* in_sizes, int n_in,
                              void* d_out, int out_size)
{
    const float* inputs = (const float*)d_in[0];
    const float* prob   = (const float*)d_in[1];
    const float* Wioux  = (const float*)d_in[2];
    const float* bioux  = (const float*)d_in[3];
    const float* Wiouh  = (const float*)d_in[4];
    const float* biouh  = (const float*)d_in[5];
    const float* Wfx    = (const float*)d_in[6];
    const float* bfx    = (const float*)d_in[7];
    const float* Wfh    = (const float*)d_in[8];
    const float* bfh    = (const float*)d_in[9];
    float* out = (float*)d_out;

    u16 *pxhi,*phhi,*pshi,*phf,*pfx,*piou;
    u16 *pWxh,*pWhh,*pWfxh,*pWfhh;
    cudaGetSymbolAddress((void**)&pxhi,  g_xhi);
    cudaGetSymbolAddress((void**)&phhi,  g_hhi);
    cudaGetSymbolAddress((void**)&pshi,  g_shi);
    cudaGetSymbolAddress((void**)&pWxh,  g_Wxh);
    cudaGetSymbolAddress((void**)&pWhh,  g_Whh);
    cudaGetSymbolAddress((void**)&pWfxh, g_Wfxh);
    cudaGetSymbolAddress((void**)&pWfhh, g_Wfhh);
    cudaGetSymbolAddress((void**)&phf,   g_hf);
    cudaGetSymbolAddress((void**)&pfx,   g_fx);
    cudaGetSymbolAddress((void**)&piou,  g_iou);

    cudaFuncSetAttribute(gemm_pair, cudaFuncAttributeMaxDynamicSharedMemorySize, SMEM_PLAIN);
    cudaFuncSetAttribute(gemm_leaf, cudaFuncAttributeMaxDynamicSharedMemorySize, SMEM_LEAF);

    const int MPAR = N_PAR*BDIM;   // 37440

    // 0: merged fp16 conversion
    split_all_kernel<<<(unsigned)((NSPLIT_TOT+255)/256),256>>>(
        inputs, Wioux, Wiouh, Wfx, Wfh,
        pxhi, pWxh, pWhh, pWfxh, pWfhh);

    // 1: leaf level fused GEMM + activation
    gemm_leaf<<<dim3(4,2048),256,SMEM_LEAF>>>(
        pxhi + (size_t)LEAF_START*NS,
        pWxh, bioux, biouh, 4096*BDIM, LEAF_START*BDIM);

    const int starts[5] = {0, 1, 9, 73, 585};
    const int counts[5] = {1, 8, 64, 512, 4096};

    for (int d=3; d>=0; d--){
        int s = starts[d], cnt = counts[d], cs = starts[d+1];
        int Mh = cnt*8*BDIM, Mp = cnt*BDIM;

        // hsum -> fp16   (launch #2 on d=3)
        hsum_kernel<<<(cnt*NS+255)/256,256>>>(prob, s, cnt);

        // merged GEMMs: hf + iou (+ fx on d=3)  (launch #3 on d=3)
        int nHf  = 2*((Mh+127)/128);
        int nIou = 6*((Mp+127)/128);
        int nFx  = (d==3) ? 2*((MPAR+127)/128) : 0;
        gemm_pair<<<nHf+nIou+nFx,256,SMEM_PLAIN>>>(
            nHf, nIou,
            phhi + (size_t)cs*NS, pWfhh, phf, Mh,
            pxhi + (size_t)s*NS, pshi, pWxh, pWhh,
            bioux, biouh, piou, Mp,
            pxhi, pWfxh, bfx, pfx, MPAR);

        // gates + activation
        if (d > 0)
            final_kernel<<<(cnt*NS+255)/256,256>>>(prob, bfh, s, cnt);
        else
            final_root_kernel<<<(NS+255)/256,256>>>(prob, bfh, out);
    }
}

// round 16
// speedup vs baseline: 1.0706x; 1.0450x over previous
#include <cuda_runtime.h>
#include <cuda_fp16.h>
#include <math.h>
#include <stdint.h>

#define N_NODES 4681
#define BDIM    64
#define NS      16384
#define LEAF_START 585
#define N_PAR   585

typedef unsigned short u16;
typedef unsigned int   u32;
typedef unsigned long long u64;

// ---------------------------------------------------------------------------
// Static device scratch (all state/intermediates fp16; out computed fp32)
// ---------------------------------------------------------------------------
__device__ __align__(256) u16   g_chi[(size_t)N_NODES*NS];
__device__ __align__(256) u16   g_hhi[(size_t)N_NODES*NS];
__device__ __align__(256) u16   g_xhi[(size_t)N_NODES*NS];
__device__ __align__(256) u16   g_hf [(size_t)4096*NS];
__device__ __align__(256) u16   g_fx [(size_t)N_PAR*NS];
__device__ __align__(256) u16   g_shi[(size_t)512*NS];
__device__ __align__(256) u16   g_iou[(size_t)512*BDIM*768];
__device__ __align__(256) u16 g_Wxh [768*256];
__device__ __align__(256) u16 g_Whh [768*256];
__device__ __align__(256) u16 g_Wfxh[256*256];
__device__ __align__(256) u16 g_Wfhh[256*256];

// ---------------------------------------------------------------------------
// Helpers
// ---------------------------------------------------------------------------
__device__ __forceinline__ float sig_fast(float x){ return 1.f/(1.f+__expf(-x)); }
__device__ __forceinline__ float tanh_fast(float x){ return 1.f - 2.f/(__expf(2.f*x)+1.f); }
__device__ __forceinline__ u16 f2h(float x){ __half h = __float2half_rn(x); return *(u16*)&h; }
__device__ __forceinline__ float h2f(u16 v){ __half h = *(__half*)&v; return __half2float(h); }

__device__ __forceinline__ u32 smem_u32(const void* p){
    u32 a; asm("{ .reg .u64 t; cvta.to.shared.u64 t, %1; cvt.u32.u64 %0, t; }" : "=r"(a) : "l"(p)); return a;
}
__device__ __forceinline__ void cp16(u32 d, const void* s){
    asm volatile("cp.async.cg.shared.global [%0], [%1], 16;" :: "r"(d), "l"(s));
}
__device__ __forceinline__ void cp_commit(){ asm volatile("cp.async.commit_group;" ::: "memory"); }
__device__ __forceinline__ void cp_wait0(){ asm volatile("cp.async.wait_group 0;" ::: "memory"); }
__device__ __forceinline__ void cp_wait1(){ asm volatile("cp.async.wait_group 1;" ::: "memory"); }

__device__ __forceinline__ void ldsm4(u32 &r0,u32 &r1,u32 &r2,u32 &r3, u32 addr){
    asm volatile("ldmatrix.sync.aligned.m8n8.x4.shared.b16 {%0,%1,%2,%3}, [%4];"
        : "=r"(r0),"=r"(r1),"=r"(r2),"=r"(r3) : "r"(addr));
}
__device__ __forceinline__ void mma16816(float* c, const u32* a, const u32* b){
    asm volatile("mma.sync.aligned.m16n8k16.row.col.f32.f16.f16.f32 "
        "{%0,%1,%2,%3}, {%4,%5,%6,%7}, {%8,%9}, {%0,%1,%2,%3};"
        : "+f"(c[0]),"+f"(c[1]),"+f"(c[2]),"+f"(c[3])
        : "r"(a[0]),"r"(a[1]),"r"(a[2]),"r"(a[3]), "r"(b[0]),"r"(b[1]));
}

#define SWZ(o) ((u32)(o) ^ (((u32)(o)>>3)&0x70u))

#define SMEM_PLAIN (65536 + 512)
#define SMEM_LEAF  (81920 + 768)

// ---------------------------------------------------------------------------
// Merged fp32 -> fp16 conversion
// ---------------------------------------------------------------------------
#define NX4  ((size_t)N_NODES*NS/4)
#define NW1  (768*256/4)
#define NW3  (256*256/4)
#define NSPLIT_TOT (NX4 + NW1*2 + NW3*2)

__global__ void split_all_kernel(
    const float* __restrict__ inputs,
    const float* __restrict__ Wioux, const float* __restrict__ Wiouh,
    const float* __restrict__ Wfx,   const float* __restrict__ Wfh,
    u16* __restrict__ xhi,
    u16* __restrict__ Wxh, u16* __restrict__ Whh,
    u16* __restrict__ Wfxh, u16* __restrict__ Wfhh)
{
    size_t i = (size_t)blockIdx.x*blockDim.x + threadIdx.x;
    if (i >= NSPLIT_TOT) return;
    const float* src; u16* dst; size_t k;
    if (i < NX4){ src=inputs; dst=xhi; k=i; }
    else {
        size_t r = i - NX4;
        if (r < NW1){ src=Wioux; dst=Wxh; k=r; }
        else if (r < 2*(size_t)NW1){ src=Wiouh; dst=Whh; k=r-NW1; }
        else if (r < 2*(size_t)NW1+NW3){ src=Wfx; dst=Wfxh; k=r-2*NW1; }
        else { src=Wfh; dst=Wfhh; k=r-2*NW1-NW3; }
    }
    float4 v = ((const float4*)src)[k];
    ((ushort4*)dst)[k] = make_ushort4(f2h(v.x), f2h(v.y), f2h(v.z), f2h(v.w));
}

// ---------------------------------------------------------------------------
// Chunk loaders (256 threads)
// ---------------------------------------------------------------------------
__device__ __forceinline__ void load_A_chunk(u32 aB, const u16* __restrict__ Ah,
    int rowBase, int kc, int M, int t)
{
#pragma unroll
    for (int i=0;i<4;i++){
        int e = t + i*256; int r = e>>3, s = e&7;
        int gr = rowBase + r; if (gr >= M) gr = M-1;
        cp16(aB + SWZ(r*128 + s*16), Ah + (size_t)gr*256 + kc + s*8);
    }
}
__device__ __forceinline__ void load_B_chunk128(u32 bB, const u16* __restrict__ Wh,
    int n0, int kc, int t)
{
#pragma unroll
    for (int i=0;i<4;i++){
        int e = t + i*256; int n = e>>3, s = e&7;
        cp16(bB + SWZ(n*128 + s*16), Wh + (size_t)(n0+n)*256 + kc + s*8);
    }
}

// ---------------------------------------------------------------------------
// Shared GEMM body: 256 threads, 8 warps (4m x 2n), warp tile 32x64.
// ---------------------------------------------------------------------------
__device__ __forceinline__ void gemm_body(
    char* smem,
    const u16* __restrict__ A1h, const u16* __restrict__ A2h,
    const u16* __restrict__ W1h, const u16* __restrict__ W2h,
    const float* __restrict__ b1, const float* __restrict__ b2,
    u16* __restrict__ Cout, int M, int ldc, int n0, int rowBase)
{
    const u32 sb = smem_u32(smem);
    const int t = threadIdx.x;
    float* biasS = (float*)(smem + 65536);

    for (int i=t;i<128;i+=256){
        float v = 0.f;
        if (b1) v += b1[n0+i];
        if (b2) v += b2[n0+i];
        biasS[i] = v;
    }

    float C[2][8][4];
#pragma unroll
    for (int a=0;a<2;a++)
#pragma unroll
    for (int b=0;b<8;b++)
#pragma unroll
    for (int cc=0;cc<4;cc++) C[a][b][cc]=0.f;

    const int nc = (A2h != nullptr) ? 8 : 4;

#define SEL_A(c) (((c)<4) ? A1h : A2h)
#define SEL_W(c) (((c)<4) ? W1h : W2h)
#define KC(c)    (((c)&3)*64)

    load_A_chunk(sb, SEL_A(0), rowBase, KC(0), M, t);
    load_B_chunk128(sb + 32768u, SEL_W(0), n0, KC(0), t);
    cp_commit();

    const int lane=t&31, wid=t>>5;
    const int wm=(wid&3)*32, wn=(wid>>2)*64;
    const u32 aRow  = (u32)(wm + (lane&15));
    const u32 aCol0 = (u32)((lane>>4)*16);
    const u32 bRow  = (u32)(wn + (lane&7) + ((lane>>4)&1)*8);
    const u32 bCol0 = (u32)(((lane>>3)&1)*16);

    for (int c=0;c<nc;c++){
        if (c+1<nc){
            int nb=(c+1)&1;
            load_A_chunk(sb + nb*16384u, SEL_A(c+1), rowBase, KC(c+1), M, t);
            load_B_chunk128(sb + 32768u + nb*16384u, SEL_W(c+1), n0, KC(c+1), t);
            cp_commit();
            cp_wait1();
        } else cp_wait0();
        __syncthreads();

        const u32 aB = sb + (u32)(c&1)*16384u;
        const u32 bB = sb + 32768u + (u32)(c&1)*16384u;
#pragma unroll
        for (int ks=0;ks<4;ks++){
            u32 a0[4], a1[4];
            ldsm4(a0[0],a0[1],a0[2],a0[3], aB + SWZ(aRow*128      + ks*32 + aCol0));
            ldsm4(a1[0],a1[1],a1[2],a1[3], aB + SWZ((aRow+16)*128 + ks*32 + aCol0));
#pragma unroll
            for (int nb=0;nb<4;nb++){
                u32 bf[4];
                ldsm4(bf[0],bf[1],bf[2],bf[3], bB + SWZ((bRow+nb*16)*128 + ks*32 + bCol0));
                mma16816(C[0][2*nb+0], a0, bf+0); mma16816(C[0][2*nb+1], a0, bf+2);
                mma16816(C[1][2*nb+0], a1, bf+0); mma16816(C[1][2*nb+1], a1, bf+2);
            }
        }
        if (c+1<nc) __syncthreads();
    }
#undef SEL_A
#undef SEL_W
#undef KC

#pragma unroll
    for (int mt=0;mt<2;mt++){
        int r0 = rowBase + wm + mt*16 + (lane>>2);
#pragma unroll
        for (int nt=0;nt<8;nt++){
            int cl = wn + nt*8 + (lane&3)*2;
            float bz0 = biasS[cl], bz1 = biasS[cl+1];
            if (r0 < M){
                u32 pk = (u32)f2h(C[mt][nt][0]+bz0) | ((u32)f2h(C[mt][nt][1]+bz1)<<16);
                *(u32*)(Cout + (size_t)r0*ldc + n0 + cl) = pk;
            }
            if (r0+8 < M){
                u32 pk = (u32)f2h(C[mt][nt][2]+bz0) | ((u32)f2h(C[mt][nt][3]+bz1)<<16);
                *(u32*)(Cout + (size_t)(r0+8)*ldc + n0 + cl) = pk;
            }
        }
    }
}

// ---------------------------------------------------------------------------
// gemm_pair: one launch = hf blocks + iou blocks + (fx blocks, d=3 only)
// ---------------------------------------------------------------------------
__global__ void __launch_bounds__(256,2) gemm_pair(
    int nHf, int nIou,
    const u16* __restrict__ hA, const u16* __restrict__ hW,
    u16* __restrict__ hC, int hM,
    const u16* __restrict__ iA1, const u16* __restrict__ iA2,
    const u16* __restrict__ iW1, const u16* __restrict__ iW2,
    const float* __restrict__ ib1, const float* __restrict__ ib2,
    u16* __restrict__ iC, int iM,
    const u16* __restrict__ fA, const u16* __restrict__ fW,
    const float* __restrict__ fB, u16* __restrict__ fC, int fM)
{
    extern __shared__ __align__(1024) char smem[];
    int bid = blockIdx.x;
    if (bid < nHf){
        gemm_body(smem, hA, nullptr, hW, nullptr, nullptr, nullptr,
                  hC, hM, 256, (bid&1)*128, (bid>>1)*128);
    } else if (bid < nHf + nIou){
        bid -= nHf;
        gemm_body(smem, iA1, iA2, iW1, iW2, ib1, ib2,
                  iC, iM, 768, (bid%6)*128, (bid/6)*128);
    } else {
        bid -= nHf + nIou;
        gemm_body(smem, fA, nullptr, fW, nullptr, fB, nullptr,
                  fC, fM, 256, (bid&1)*128, (bid>>1)*128);
    }
}

// ---------------------------------------------------------------------------
// gemm_leaf: fused iou GEMM + LSTM activation; c and h stored fp16.
// ---------------------------------------------------------------------------
__global__ void __launch_bounds__(256,2) gemm_leaf(
    const u16* __restrict__ Ah_,
    const u16* __restrict__ Wh_,
    const float* __restrict__ bx, const float* __restrict__ bh,
    int M, int outRowBase)
{
    extern __shared__ __align__(1024) char smem[];
    const u32 sb = smem_u32(smem);
    const int t = threadIdx.x;
    const int m0 = blockIdx.x*64;
    const int rowBase = blockIdx.y*128;
    float* biasS = (float*)(smem + 81920);

    for (int i=t;i<192;i+=256){
        int g=i>>6, cc=i&63;
        biasS[i] = bx[g*256+m0+cc] + bh[g*256+m0+cc];
    }

    float Cg[3][2][4][4];
#pragma unroll
    for (int g=0;g<3;g++)
#pragma unroll
    for (int a=0;a<2;a++)
#pragma unroll
    for (int b=0;b<4;b++)
#pragma unroll
    for (int cc=0;cc<4;cc++) Cg[g][a][b][cc]=0.f;

#define LOAD_LEAF_B(bB, kc) \
    { _Pragma("unroll") \
      for (int i=0;i<6;i++){ \
        int e = t + i*256; int g = e>>9, f = e&511, n = f>>3, s = f&7; \
        cp16((bB) + (u32)g*8192u + SWZ(n*128 + s*16), \
             Wh_ + (size_t)(g*256 + m0 + n)*256 + (kc) + s*8); } }

    load_A_chunk(sb, Ah_, rowBase, 0, M, t);
    LOAD_LEAF_B(sb + 32768u, 0);
    cp_commit();

    const int lane=t&31, wid=t>>5;
    const int wm=(wid&3)*32, wn=(wid>>2)*32;
    const u32 aRow  = (u32)(wm + (lane&15));
    const u32 aCol0 = (u32)((lane>>4)*16);
    const u32 bRow  = (u32)(wn + (lane&7) + ((lane>>4)&1)*8);
    const u32 bCol0 = (u32)(((lane>>3)&1)*16);

    for (int c=0;c<4;c++){
        cp_wait0();
        __syncthreads();
        if (c+1<4){
            int nb=(c+1)&1;
            load_A_chunk(sb + nb*16384u, Ah_, rowBase, (c+1)*64, M, t);
            LOAD_LEAF_B(sb + 32768u + (u32)nb*24576u, (c+1)*64);
            cp_commit();
        }
        const u32 aB = sb + (u32)(c&1)*16384u;
        const u32 bB = sb + 32768u + (u32)(c&1)*24576u;
#pragma unroll
        for (int ks=0;ks<4;ks++){
            u32 a0[4], a1[4];
            ldsm4(a0[0],a0[1],a0[2],a0[3], aB + SWZ(aRow*128      + ks*32 + aCol0));
            ldsm4(a1[0],a1[1],a1[2],a1[3], aB + SWZ((aRow+16)*128 + ks*32 + aCol0));
#pragma unroll
            for (int g=0;g<3;g++){
                u32 b0[4], b1f[4];
                u32 gB = bB + (u32)g*8192u;
                ldsm4(b0[0],b0[1],b0[2],b0[3],   gB + SWZ(bRow*128      + ks*32 + bCol0));
                ldsm4(b1f[0],b1f[1],b1f[2],b1f[3], gB + SWZ((bRow+16)*128 + ks*32 + bCol0));
                mma16816(Cg[g][0][0], a0, b0+0); mma16816(Cg[g][0][1], a0, b0+2);
                mma16816(Cg[g][0][2], a0, b1f+0); mma16816(Cg[g][0][3], a0, b1f+2);
                mma16816(Cg[g][1][0], a1, b0+0); mma16816(Cg[g][1][1], a1, b0+2);
                mma16816(Cg[g][1][2], a1, b1f+0); mma16816(Cg[g][1][3], a1, b1f+2);
            }
        }
    }
#undef LOAD_LEAF_B

#pragma unroll
    for (int mt=0;mt<2;mt++){
        int rb = wm + mt*16 + (lane>>2);
#pragma unroll
        for (int h2=0;h2<2;h2++){
            int row = rowBase + rb + h2*8;
#pragma unroll
            for (int nt=0;nt<4;nt++){
                int cl = wn + nt*8 + (lane&3)*2;
                u16 cc2[2], hh2[2];
#pragma unroll
                for (int e=0;e<2;e++){
                    float iv = Cg[0][mt][nt][h2*2+e] + biasS[cl+e];
                    float ov = Cg[1][mt][nt][h2*2+e] + biasS[64+cl+e];
                    float uv = Cg[2][mt][nt][h2*2+e] + biasS[128+cl+e];
                    float c_ = sig_fast(iv)*tanh_fast(uv);
                    float h_ = sig_fast(ov)*tanh_fast(c_);
                    cc2[e]=f2h(c_);
                    hh2[e]=f2h(h_);
                }
                size_t idx = ((size_t)(outRowBase+row))*256 + m0 + cl;
                *(u32*)(g_chi+idx) = (u32)cc2[0] | ((u32)cc2[1]<<16);
                *(u32*)(g_hhi+idx) = (u32)hh2[0] | ((u32)hh2[1]<<16);
            }
        }
    }
}

// ---------------------------------------------------------------------------
// hsum: reads h-hi; fp16 output
// ---------------------------------------------------------------------------
__global__ void hsum_kernel(const float* __restrict__ prob, int s, int cnt)
{
    int idx = blockIdx.x*blockDim.x + threadIdx.x;
    if (idx >= cnt*NS) return;
    int p = idx >> 14, r = idx & (NS-1);
    int pg = s + p, cg = 8*pg + 1;
    const float* pr = prob + (size_t)pg*N_NODES + cg;
    float acc = 0.f;
#pragma unroll
    for (int j=0;j<8;j++)
        acc += pr[j] * h2f(g_hhi[(size_t)(cg+j)*NS + r]);
    g_shi[idx] = f2h(acc);
}

// ---------------------------------------------------------------------------
// final: forget gates + cell/hidden activation (levels d=3..1); fp16 state
// ---------------------------------------------------------------------------
__global__ void final_kernel(const float* __restrict__ prob,
                             const float* __restrict__ bfh, int s, int cnt)
{
    int idx = blockIdx.x*blockDim.x + threadIdx.x;
    if (idx >= cnt*NS) return;
    int p = idx >> 14, r = idx & (NS-1);
    int m = idx & 255;
    int row = idx >> 8;
    int pg = s + p, cg = 8*pg + 1;

    const u16* iou = g_iou + (size_t)row*768 + m;
    float iv = h2f(iou[0]), ov = h2f(iou[256]), uv = h2f(iou[512]);
    float fxv = h2f(g_fx[(size_t)pg*NS + r]);
    float bf = bfh[m];

    const float* pr = prob + (size_t)pg*N_NODES + cg;
    float acc = 0.f;
#pragma unroll
    for (int j=0;j<8;j++){
        float pw  = pr[j];
        float hf  = h2f(g_hf[(size_t)(8*p+j)*NS + r]);
        float cch = h2f(g_chi[(size_t)(cg+j)*NS + r]);
        float f = sig_fast(pw*hf + bf + fxv);
        acc += f * pw * cch;
    }
    float cc = sig_fast(iv)*tanh_fast(uv) + acc;
    float hh = sig_fast(ov)*tanh_fast(cc);
    g_chi[(size_t)pg*NS + r] = f2h(cc);
    g_hhi[(size_t)pg*NS + r] = f2h(hh);
}

// ---------------------------------------------------------------------------
// final_root: finalize node 0 and write out directly (fp32 out).
// ---------------------------------------------------------------------------
__global__ void final_root_kernel(const float* __restrict__ prob,
                                  const float* __restrict__ bfh,
                                  float* __restrict__ out)
{
    int r = blockIdx.x*blockDim.x + threadIdx.x;
    if (r >= NS) return;
    int m = r & 255;

    const u16* iou = g_iou + (size_t)(r>>8)*768 + m;
    float iv = h2f(iou[0]), ov = h2f(iou[256]), uv = h2f(iou[512]);
    float fxv = h2f(g_fx[r]);
    float bf = bfh[m];

    const float* pr = prob + 1;   // prob[0, 1..8]
    float acc = 0.f;
#pragma unroll
    for (int j=0;j<8;j++){
        float pw  = pr[j];
        float hf  = h2f(g_hf[(size_t)j*NS + r]);
        float cch = h2f(g_chi[(size_t)(1+j)*NS + r]);
        float f = sig_fast(pw*hf + bf + fxv);
        acc += f * pw * cch;
    }
    float cc = sig_fast(iv)*tanh_fast(uv) + acc;
    float hh = sig_fast(ov)*tanh_fast(cc);
    out[r]      = cc;
    out[NS + r] = hh;
}

// ---------------------------------------------------------------------------
// kernel_launch
// ---------------------------------------------------------------------------
extern "C" void kernel_launch(void* const* d_in, const int* in_sizes, int n_in,
                              void* d_out, int out_size)
{
    const float* inputs = (const float*)d_in[0];
    const float* prob   = (const float*)d_in[1];
    const float* Wioux  = (const float*)d_in[2];
    const float* bioux  = (const float*)d_in[3];
    const float* Wiouh  = (const float*)d_in[4];
    const float* biouh  = (const float*)d_in[5];
    const float* Wfx    = (const float*)d_in[6];
    const float* bfx    = (const float*)d_in[7];
    const float* Wfh    = (const float*)d_in[8];
    const float* bfh    = (const float*)d_in[9];
    float* out = (float*)d_out;

    u16 *pxhi,*phhi,*pshi,*phf,*pfx,*piou;
    u16 *pWxh,*pWhh,*pWfxh,*pWfhh;
    cudaGetSymbolAddress((void**)&pxhi,  g_xhi);
    cudaGetSymbolAddress((void**)&phhi,  g_hhi);
    cudaGetSymbolAddress((void**)&pshi,  g_shi);
    cudaGetSymbolAddress((void**)&pWxh,  g_Wxh);
    cudaGetSymbolAddress((void**)&pWhh,  g_Whh);
    cudaGetSymbolAddress((void**)&pWfxh, g_Wfxh);
    cudaGetSymbolAddress((void**)&pWfhh, g_Wfhh);
    cudaGetSymbolAddress((void**)&phf,   g_hf);
    cudaGetSymbolAddress((void**)&pfx,   g_fx);
    cudaGetSymbolAddress((void**)&piou,  g_iou);

    cudaFuncSetAttribute(gemm_pair, cudaFuncAttributeMaxDynamicSharedMemorySize, SMEM_PLAIN);
    cudaFuncSetAttribute(gemm_leaf, cudaFuncAttributeMaxDynamicSharedMemorySize, SMEM_LEAF);

    const int MPAR = N_PAR*BDIM;   // 37440

    // 0: merged fp16 conversion
    split_all_kernel<<<(unsigned)((NSPLIT_TOT+255)/256),256>>>(
        inputs, Wioux, Wiouh, Wfx, Wfh,
        pxhi, pWxh, pWhh, pWfxh, pWfhh);

    // 1: leaf level fused GEMM + activation
    gemm_leaf<<<dim3(4,2048),256,SMEM_LEAF>>>(
        pxhi + (size_t)LEAF_START*NS,
        pWxh, bioux, biouh, 4096*BDIM, LEAF_START*BDIM);

    const int starts[5] = {0, 1, 9, 73, 585};
    const int counts[5] = {1, 8, 64, 512, 4096};

    for (int d=3; d>=0; d--){
        int s = starts[d], cnt = counts[d], cs = starts[d+1];
        int Mh = cnt*8*BDIM, Mp = cnt*BDIM;

        // hsum -> fp16   (launch #2 on d=3)
        hsum_kernel<<<(cnt*NS+255)/256,256>>>(prob, s, cnt);

        // merged GEMMs: hf + iou (+ fx on d=3)  (launch #3 on d=3)
        int nHf  = 2*((Mh+127)/128);
        int nIou = 6*((Mp+127)/128);
        int nFx  = (d==3) ? 2*((MPAR+127)/128) : 0;
        gemm_pair<<<nHf+nIou+nFx,256,SMEM_PLAIN>>>(
            nHf, nIou,
            phhi + (size_t)cs*NS, pWfhh, phf, Mh,
            pxhi + (size_t)s*NS, pshi, pWxh, pWhh,
            bioux, biouh, piou, Mp,
            pxhi, pWfxh, bfx, pfx, MPAR);

        // gates + activation
        if (d > 0)
            final_kernel<<<(cnt*NS+255)/256,256>>>(prob, bfh, s, cnt);
        else
            final_root_kernel<<<(NS+255)/256,256>>>(prob, bfh, out);
    }
}